// round 7
// baseline (speedup 1.0000x reference)
#include <cuda_runtime.h>

// Problem dims
#define NB   8
#define NC   64
#define NT   16
#define NH   56
#define NW   56
#define NHID 128
#define NHP  28
#define NWP  28
#define NK   4

// Kernel-1 tiling
#define IHT  9
#define NPOS (IHT*NW)
#define CSTR 58
#define RSTR (NC*CSTR + 8)
#define SX_F (IHT*RSTR)
#define WD_F (32*NC*2)
#define BUF_F (32*NPOS)
#define SMEM1_F (SX_F + WD_F + BUF_F)

__device__ float g_pooled[NB*NHID*NT*NHP*NWP];   // [b][ch][t][28*28]
__device__ float g_e[NB*NT*NHP*NWP];             // e values [b][t][784]
__device__ int   g_tpos[NB*NK];

__device__ __forceinline__ unsigned long long ld_u64(const float* p) {
    return *reinterpret_cast<const unsigned long long*>(p);
}

// ---------------------------------------------------------------------------
// Kernel 1: conv1x1 (64->128) + bias + ReLU + maxpool 3x3/s2, exact fp32.
// Per-output accumulation: sequential c=0..63 ascending FMA chain from 0
// (emulates Eigen GEMM per-output chain bit-exactly).
// ---------------------------------------------------------------------------
__global__ __launch_bounds__(256, 1) void k_conv_pool(
    const float* __restrict__ x, const float* __restrict__ w1, const float* __restrict__ b1)
{
    extern __shared__ float sm[];
    float* sx  = sm;                 // [9][64][58(+pad)]
    float* swd = sm + SX_F;          // [32][64][2] duplicated weight pairs
    float* buf = sm + SX_F + WD_F;   // [32][504]

    int blk = blockIdx.x;
    int ohg = blk % 7;
    int tt  = (blk / 7) % NT;
    int b   = blk / (7*NT);
    int ih0 = ohg*8 - 1;
    int tid = threadIdx.x;

    const float* xbt = x + (b*NC*NT + tt)*(NH*NW);
    for (int i = tid; i < IHT*NC*NW; i += 256) {
        int col = i % NW;
        int cc  = (i / NW) % NC;
        int r   = i / (NW*NC);
        int ih  = ih0 + r;
        float v = (ih >= 0 && ih < NH) ? xbt[cc*(NT*NH*NW) + ih*NW + col] : 0.f;
        sx[r*RSTR + cc*CSTR + col] = v;
    }

    int wid  = tid >> 5, lane = tid & 31;
    int half = wid >> 2;
    int sub  = wid & 3;

    const float* xptr[4];
    int  p_[4];
    bool val[4];
    #pragma unroll
    for (int j = 0; j < 4; j++) {
        int p = half*256 + j*64 + 2*lane;
        val[j] = (p < NPOS);
        int pc = val[j] ? p : 0;
        int r  = pc / NW, cl = pc % NW;
        xptr[j] = sx + r*RSTR + cl;
        p_[j] = pc;
    }

    for (int it = 0; it < 4; it++) {
        int ch0 = it*32;
        __syncthreads();
        for (int i = tid; i < 32*NC; i += 256) {
            float v = w1[(ch0 + i/NC)*NC + (i % NC)];
            swd[2*i] = v; swd[2*i+1] = v;
        }
        __syncthreads();

        unsigned long long acc[4][8];
        #pragma unroll
        for (int j = 0; j < 4; j++)
            #pragma unroll
            for (int q = 0; q < 8; q++) acc[j][q] = 0ull;

        const float* wbase = swd + (sub*8)*NC*2;
        #pragma unroll 2
        for (int c = 0; c < NC; c++) {
            unsigned long long xv[4];
            #pragma unroll
            for (int j = 0; j < 4; j++) xv[j] = ld_u64(xptr[j] + c*CSTR);
            #pragma unroll
            for (int q = 0; q < 8; q++) {
                unsigned long long wv = ld_u64(wbase + (q*NC + c)*2);
                #pragma unroll
                for (int j = 0; j < 4; j++)
                    asm("fma.rn.f32x2 %0, %1, %2, %0;" : "+l"(acc[j][q]) : "l"(wv), "l"(xv[j]));
            }
        }

        #pragma unroll
        for (int q = 0; q < 8; q++) {
            int co = sub*8 + q;
            float bj = b1[ch0 + co];
            #pragma unroll
            for (int j = 0; j < 4; j++) {
                float a0, a1;
                asm("mov.b64 {%0,%1}, %2;" : "=f"(a0), "=f"(a1) : "l"(acc[j][q]));
                a0 = fmaxf(__fadd_rn(a0, bj), 0.f);
                a1 = fmaxf(__fadd_rn(a1, bj), 0.f);
                if (val[j]) {
                    float2 v2 = make_float2(a0, a1);
                    *reinterpret_cast<float2*>(&buf[co*NPOS + p_[j]]) = v2;
                }
            }
        }
        __syncthreads();

        // maxpool 3x3/s2 pad1 (max is order-exact)
        for (int m = tid; m < 4*28*32; m += 256) {
            int oc  = m % 28;
            int orr = (m / 28) & 3;
            int co  = m / 112;
            float mx = 0.f;
            #pragma unroll
            for (int dy = 0; dy < 3; dy++) {
                int lr = 2*orr + dy;
                int gr = ih0 + lr;
                if (gr < 0 || gr >= NH) continue;
                #pragma unroll
                for (int dx = 0; dx < 3; dx++) {
                    int gc = 2*oc - 1 + dx;
                    if (gc < 0 || gc >= NW) continue;
                    mx = fmaxf(mx, buf[co*NPOS + lr*NW + gc]);
                }
            }
            int ch = ch0 + co;
            g_pooled[((b*NHID + ch)*NT + tt)*(NHP*NWP) + (ohg*4 + orr)*NWP + oc] = mx;
        }
    }
}

// ---------------------------------------------------------------------------
// Kernel 2: depthwise 3x3 (pad 1) + bias + ReLU + 1x1 (128->1) + b2.
// Emitter emulation: per output position,
//   acc over ch = 0..127 sequential single chain, mul+add NO FMA;
//   per-channel dw: taps ky,kx ascending, mul+add NO FMA.
// Block = (b,t), 256 threads, channel-staged through smem.
// ---------------------------------------------------------------------------
__global__ __launch_bounds__(256) void k_dw2(
    const float* __restrict__ wd, const float* __restrict__ bd,
    const float* __restrict__ w2, const float* __restrict__ b2)
{
    __shared__ float tile[NHP*NWP];     // one channel's pooled 28x28
    __shared__ float swdk[NHID*9];
    __shared__ float sbd[NHID], sw2[NHID];

    int bid = blockIdx.x;
    int tt = bid % NT;
    int b  = bid / NT;
    int tid = threadIdx.x;

    for (int i = tid; i < NHID*9; i += 256) swdk[i] = wd[i];
    for (int i = tid; i < NHID;   i += 256) { sbd[i] = bd[i]; sw2[i] = w2[i]; }
    float b2v = b2[0];

    float acc[4] = {0.f, 0.f, 0.f, 0.f};
    int y_[4], x_[4]; bool ok[4];
    #pragma unroll
    for (int s = 0; s < 4; s++) {
        int p = tid + s*256;
        ok[s] = (p < 784);
        int pc = ok[s] ? p : 0;
        y_[s] = pc / 28; x_[s] = pc % 28;
    }

    for (int ch = 0; ch < NHID; ch++) {
        __syncthreads();
        const float* src = &g_pooled[((b*NHID + ch)*NT + tt)*784];
        for (int i = tid; i < 784; i += 256) tile[i] = src[i];
        __syncthreads();

        float w2c = sw2[ch], bdc = sbd[ch];
        const float* wk = &swdk[ch*9];
        #pragma unroll
        for (int s = 0; s < 4; s++) {
            if (!ok[s]) continue;
            int y = y_[s], xx = x_[s];
            float v = 0.f;
            #pragma unroll
            for (int ky = 0; ky < 3; ky++) {
                int yy = y + ky - 1;
                if (yy < 0 || yy >= 28) continue;
                #pragma unroll
                for (int kx = 0; kx < 3; kx++) {
                    int xc = xx + kx - 1;
                    if (xc < 0 || xc >= 28) continue;
                    v = __fadd_rn(v, __fmul_rn(wk[ky*3 + kx], tile[yy*28 + xc]));
                }
            }
            float hv = fmaxf(__fadd_rn(v, bdc), 0.f);
            acc[s] = __fadd_rn(acc[s], __fmul_rn(w2c, hv));
        }
    }
    #pragma unroll
    for (int s = 0; s < 4; s++) {
        int p = tid + s*256;
        if (p < 784) g_e[(b*NT + tt)*784 + p] = __fadd_rn(acc[s], b2v);
    }
}

// ---------------------------------------------------------------------------
// Kernel 3: segmentation, XLA:CPU-emitter emulation.
// All reductions: sequential ascending, mul+add NO FMA. Elementwise div RN.
// 8 blocks x 64 threads.
// ---------------------------------------------------------------------------
__global__ __launch_bounds__(64) void k_seg(const float* __restrict__ dummy)
{
    extern __shared__ float sm[];
    float* sen = sm;                 // [16][784] ne
    float* cen = sm + 16*784;        // [4][784] centers
    float* snc = sm + 20*784;        // [4][784] normalized centers
    __shared__ float snorm[16], snsim[15], scnorm[4];
    __shared__ float ssims[16][4];
    __shared__ int sgroups[16], sgsize[4];

    int b = blockIdx.x, tid = threadIdx.x;

    for (int i = tid; i < 16*784; i += 64)
        sen[i] = g_e[b*NT*784 + i];
    __syncthreads();

    // per-frame norms: sequential d=0..783, mul+add, no FMA
    if (tid < 16) {
        float s = 0.f;
        const float* row = &sen[tid*784];
        for (int d = 0; d < 784; d++) s = __fadd_rn(s, __fmul_rn(row[d], row[d]));
        snorm[tid] = fmaxf(__fsqrt_rn(s), 1e-12f);
    }
    __syncthreads();

    // normalize elementwise (RN division)
    for (int i = tid; i < 16*784; i += 64) sen[i] = __fdiv_rn(sen[i], snorm[i / 784]);
    __syncthreads();

    // neighbor sims: sequential d, mul+add
    if (tid < 15) {
        float s = 0.f;
        const float* r0 = &sen[tid*784];
        const float* r1 = &sen[(tid+1)*784];
        for (int d = 0; d < 784; d++) s = __fadd_rn(s, __fmul_rn(r0[d], r1[d]));
        snsim[tid] = s;
    }
    __syncthreads();

    if (tid == 0) {
        int used[15]; int breaks[15];
        for (int i = 0; i < 15; i++) { used[i] = 0; breaks[i] = 0; }
        for (int k = 0; k < 3; k++) {
            float best = 1e30f; int bi = 0;
            for (int i = 0; i < 15; i++)
                if (!used[i] && snsim[i] < best) { best = snsim[i]; bi = i; }
            used[bi] = 1; breaks[bi] = 1;
        }
        int g = 0;
        for (int t = 0; t < 16; t++) { if (t > 0) g += breaks[t-1]; sgroups[t] = g; }
        for (int k = 0; k < 4; k++) sgsize[k] = 0;
        for (int t = 0; t < 16; t++) sgsize[sgroups[t]]++;
    }
    __syncthreads();

    // centers: contraction over t=0..15 ascending (zeros from mask are exact no-ops)
    for (int d = tid; d < 784; d += 64) {
        float c4[4] = {0.f, 0.f, 0.f, 0.f};
        for (int t = 0; t < 16; t++)
            c4[sgroups[t]] = __fadd_rn(c4[sgroups[t]], sen[t*784 + d]);
        for (int k = 0; k < 4; k++)
            cen[k*784 + d] = __fdiv_rn(c4[k], (float)sgsize[k]);
    }
    __syncthreads();

    // center norms: sequential d
    if (tid < 4) {
        float s = 0.f;
        const float* ck = &cen[tid*784];
        for (int d = 0; d < 784; d++) s = __fadd_rn(s, __fmul_rn(ck[d], ck[d]));
        scnorm[tid] = fmaxf(__fsqrt_rn(s), 1e-12f);
    }
    __syncthreads();

    // nc materialized elementwise (matches reference's nc tensor)
    for (int i = tid; i < 4*784; i += 64)
        snc[i] = __fdiv_rn(cen[i], scnorm[i / 784]);
    __syncthreads();

    // sims: 64 dots, one per thread, sequential d, mul+add
    {
        int t = tid / 4, k = tid % 4;
        const float* row = &sen[t*784];
        const float* ck = &snc[k*784];
        float s = 0.f;
        for (int d = 0; d < 784; d++)
            s = __fadd_rn(s, __fmul_rn(row[d], ck[d]));
        ssims[t][k] = fminf(fmaxf(s, -1.f), 1.f);
    }
    __syncthreads();

    // argmax over t (first max) of sims*gmask
    if (tid < 4) {
        int k = tid;
        float best = -1e30f; int bt = 0;
        for (int t = 0; t < 16; t++) {
            float v = (sgroups[t] == k) ? ssims[t][k] : 0.f;
            if (v > best) { best = v; bt = t; }
        }
        g_tpos[b*NK + k] = bt;
    }
}

// ---------------------------------------------------------------------------
// Kernel 4: gather selected frames
// ---------------------------------------------------------------------------
__global__ __launch_bounds__(256) void k_gather(const float* __restrict__ x, float* __restrict__ out)
{
    int idx = blockIdx.x*256 + threadIdx.x;
    const int total = NB*NC*NK*784;
    if (idx >= total) return;
    int hw4 = idx % 784;
    int t1  = idx / 784;
    int k   = t1 % 4;  t1 /= 4;
    int c   = t1 % 64;
    int b   = t1 / 64;
    int t   = g_tpos[b*NK + k];
    float4 v = reinterpret_cast<const float4*>(x)[((b*NC + c)*NT + t)*784 + hw4];
    reinterpret_cast<float4*>(out)[idx] = v;
}

// ---------------------------------------------------------------------------
extern "C" void kernel_launch(void* const* d_in, const int* in_sizes, int n_in,
                              void* d_out, int out_size)
{
    const float* x  = (const float*)d_in[0];
    const float* w1 = (const float*)d_in[1];
    const float* b1 = (const float*)d_in[2];
    const float* wd = (const float*)d_in[3];
    const float* bd = (const float*)d_in[4];
    const float* w2 = (const float*)d_in[5];
    const float* b2 = (const float*)d_in[6];
    float* out = (float*)d_out;

    cudaFuncSetAttribute(k_conv_pool, cudaFuncAttributeMaxDynamicSharedMemorySize, SMEM1_F*4);
    cudaFuncSetAttribute(k_seg, cudaFuncAttributeMaxDynamicSharedMemorySize, 24*784*4);

    k_conv_pool<<<NB*NT*7, 256, SMEM1_F*4>>>(x, w1, b1);
    k_dw2<<<NB*NT, 256>>>(wd, bd, w2, b2);
    k_seg<<<NB, 64, 24*784*4>>>(nullptr);
    const int total4 = NB*NC*NK*784;
    k_gather<<<(total4 + 255)/256, 256>>>(x, out);
}

// round 8
// speedup vs baseline: 1.4139x; 1.4139x over previous
#include <cuda_runtime.h>

// Problem dims
#define NB   8
#define NC   64
#define NT   16
#define NH   56
#define NW   56
#define NHID 128
#define NHP  28
#define NWP  28
#define NK   4

// Kernel-1 tiling
#define IHT  9
#define NPOS (IHT*NW)
#define CSTR 58
#define RSTR (NC*CSTR + 8)
#define SX_F (IHT*RSTR)
#define WD_F (32*NC*2)
#define BUF_F (32*NPOS)
#define SMEM1_F (SX_F + WD_F + BUF_F)

__device__ float g_pooled[NB*NHID*NT*NHP*NWP];   // [b][ch][t][28*28]
__device__ float g_e[NB*NT*NHP*NWP];             // e values [b][t][784]
__device__ int   g_tpos[NB*NK];

__device__ __forceinline__ unsigned long long ld_u64(const float* p) {
    return *reinterpret_cast<const unsigned long long*>(p);
}

// ---------------------------------------------------------------------------
// Kernel 1: conv1x1 (64->128) + bias + ReLU + maxpool 3x3/s2, exact fp32.
// Per-output: sequential c=0..63 ascending FMA chain from 0 (Eigen-exact).
// Weight broadcasts fused as LDS.128 over channel pairs.
// ---------------------------------------------------------------------------
__global__ __launch_bounds__(256, 1) void k_conv_pool(
    const float* __restrict__ x, const float* __restrict__ w1, const float* __restrict__ b1)
{
    extern __shared__ float sm[];
    float* sx  = sm;                 // [9][64][58(+pad)]
    float* swd = sm + SX_F;          // [32][64][2] duplicated weight pairs
    float* buf = sm + SX_F + WD_F;   // [32][504]

    int blk = blockIdx.x;
    int ohg = blk % 7;
    int tt  = (blk / 7) % NT;
    int b   = blk / (7*NT);
    int ih0 = ohg*8 - 1;
    int tid = threadIdx.x;

    const float* xbt = x + (b*NC*NT + tt)*(NH*NW);
    for (int i = tid; i < IHT*NC*NW; i += 256) {
        int col = i % NW;
        int cc  = (i / NW) % NC;
        int r   = i / (NW*NC);
        int ih  = ih0 + r;
        float v = (ih >= 0 && ih < NH) ? xbt[cc*(NT*NH*NW) + ih*NW + col] : 0.f;
        sx[r*RSTR + cc*CSTR + col] = v;
    }

    int wid  = tid >> 5, lane = tid & 31;
    int half = wid >> 2;      // position half
    int sub  = wid & 3;       // channel subgroup (8 ch)

    const float* xptr[4];
    int  p_[4];
    bool val[4];
    #pragma unroll
    for (int j = 0; j < 4; j++) {
        int p = half*256 + j*64 + 2*lane;
        val[j] = (p < NPOS);
        int pc = val[j] ? p : 0;
        int r  = pc / NW, cl = pc % NW;
        xptr[j] = sx + r*RSTR + cl;
        p_[j] = pc;
    }

    for (int it = 0; it < 4; it++) {
        int ch0 = it*32;
        __syncthreads();
        for (int i = tid; i < 32*NC; i += 256) {
            float v = w1[(ch0 + i/NC)*NC + (i % NC)];
            swd[2*i] = v; swd[2*i+1] = v;
        }
        __syncthreads();

        unsigned long long acc[4][8];
        #pragma unroll
        for (int j = 0; j < 4; j++)
            #pragma unroll
            for (int q = 0; q < 8; q++) acc[j][q] = 0ull;

        const float* wbase = swd + (sub*8)*NC*2;
        for (int c = 0; c < NC; c += 2) {
            unsigned long long xv0[4], xv1[4];
            #pragma unroll
            for (int j = 0; j < 4; j++) xv0[j] = ld_u64(xptr[j] + c*CSTR);
            #pragma unroll
            for (int j = 0; j < 4; j++) xv1[j] = ld_u64(xptr[j] + (c+1)*CSTR);
            #pragma unroll
            for (int q = 0; q < 8; q++) {
                ulonglong2 wv = *reinterpret_cast<const ulonglong2*>(wbase + (q*NC + c)*2);
                #pragma unroll
                for (int j = 0; j < 4; j++)
                    asm("fma.rn.f32x2 %0, %1, %2, %0;" : "+l"(acc[j][q]) : "l"(wv.x), "l"(xv0[j]));
                #pragma unroll
                for (int j = 0; j < 4; j++)
                    asm("fma.rn.f32x2 %0, %1, %2, %0;" : "+l"(acc[j][q]) : "l"(wv.y), "l"(xv1[j]));
            }
        }

        #pragma unroll
        for (int q = 0; q < 8; q++) {
            int co = sub*8 + q;
            float bj = b1[ch0 + co];
            #pragma unroll
            for (int j = 0; j < 4; j++) {
                float a0, a1;
                asm("mov.b64 {%0,%1}, %2;" : "=f"(a0), "=f"(a1) : "l"(acc[j][q]));
                a0 = fmaxf(__fadd_rn(a0, bj), 0.f);
                a1 = fmaxf(__fadd_rn(a1, bj), 0.f);
                if (val[j]) {
                    float2 v2 = make_float2(a0, a1);
                    *reinterpret_cast<float2*>(&buf[co*NPOS + p_[j]]) = v2;
                }
            }
        }
        __syncthreads();

        for (int m = tid; m < 4*28*32; m += 256) {
            int oc  = m % 28;
            int orr = (m / 28) & 3;
            int co  = m / 112;
            float mx = 0.f;
            #pragma unroll
            for (int dy = 0; dy < 3; dy++) {
                int lr = 2*orr + dy;
                int gr = ih0 + lr;
                if (gr < 0 || gr >= NH) continue;
                #pragma unroll
                for (int dx = 0; dx < 3; dx++) {
                    int gc = 2*oc - 1 + dx;
                    if (gc < 0 || gc >= NW) continue;
                    mx = fmaxf(mx, buf[co*NPOS + lr*NW + gc]);
                }
            }
            int ch = ch0 + co;
            g_pooled[((b*NHID + ch)*NT + tt)*(NHP*NWP) + (ohg*4 + orr)*NWP + oc] = mx;
        }
    }
}

// ---------------------------------------------------------------------------
// Kernel 2: depthwise 3x3 + bias + ReLU + 1x1 (128->1) + b2.
// Thread-per-position, no barriers: ch = 0..127 sequential chain (no FMA),
// taps ky,kx ascending (no FMA). 128 blocks x 784 threads.
// ---------------------------------------------------------------------------
__global__ __launch_bounds__(784) void k_dw2(
    const float* __restrict__ wd, const float* __restrict__ bd,
    const float* __restrict__ w2, const float* __restrict__ b2)
{
    __shared__ float swdk[NHID*9];
    __shared__ float sbd[NHID], sw2[NHID];

    int bid = blockIdx.x;
    int tt = bid % NT;
    int b  = bid / NT;
    int tid = threadIdx.x;     // position 0..783

    for (int i = tid; i < NHID*9; i += 784) swdk[i] = wd[i];
    if (tid < NHID) { sbd[tid] = bd[tid]; sw2[tid] = w2[tid]; }
    float b2v = b2[0];
    __syncthreads();

    int y = tid / 28, xx = tid % 28;
    int y0 = (y > 0) ? -1 : 0, y1 = (y < 27) ? 1 : 0;
    int x0 = (xx > 0) ? -1 : 0, x1 = (xx < 27) ? 1 : 0;

    const float* base = g_pooled + (b*NHID*NT + tt)*784 + tid;
    const int chstride = NT*784;

    float acc = 0.f;
    #pragma unroll 2
    for (int ch = 0; ch < NHID; ch++) {
        const float* p = base + ch*chstride;
        const float* wk = &swdk[ch*9];
        float v = 0.f;
        #pragma unroll
        for (int ky = y0; ky <= 1; ky++) {
            if (ky > y1) break;
            #pragma unroll
            for (int kx = x0; kx <= 1; kx++) {
                if (kx > x1) break;
                v = __fadd_rn(v, __fmul_rn(wk[(ky+1)*3 + (kx+1)], __ldg(p + ky*28 + kx)));
            }
        }
        float hv = fmaxf(__fadd_rn(v, sbd[ch]), 0.f);
        acc = __fadd_rn(acc, __fmul_rn(sw2[ch], hv));
    }
    g_e[(b*NT + tt)*784 + tid] = __fadd_rn(acc, b2v);
}

// ---------------------------------------------------------------------------
// Kernel 3: segmentation, XLA:CPU-emitter emulation (bit-identical chains).
// 8 blocks x 256 threads (elementwise phases wider; reductions unchanged).
// ---------------------------------------------------------------------------
__global__ __launch_bounds__(256) void k_seg(const float* __restrict__ dummy)
{
    extern __shared__ float sm[];
    float* sen = sm;                 // [16][784] ne
    float* cen = sm + 16*784;        // [4][784] centers
    float* snc = sm + 20*784;        // [4][784] normalized centers
    __shared__ float snorm[16], snsim[15], scnorm[4];
    __shared__ float ssims[16][4];
    __shared__ int sgroups[16], sgsize[4];

    int b = blockIdx.x, tid = threadIdx.x;

    for (int i = tid; i < 16*784; i += 256)
        sen[i] = g_e[b*NT*784 + i];
    __syncthreads();

    if (tid < 16) {
        float s = 0.f;
        const float* row = &sen[tid*784];
        for (int d = 0; d < 784; d++) s = __fadd_rn(s, __fmul_rn(row[d], row[d]));
        snorm[tid] = fmaxf(__fsqrt_rn(s), 1e-12f);
    }
    __syncthreads();

    for (int i = tid; i < 16*784; i += 256) sen[i] = __fdiv_rn(sen[i], snorm[i / 784]);
    __syncthreads();

    if (tid < 15) {
        float s = 0.f;
        const float* r0 = &sen[tid*784];
        const float* r1 = &sen[(tid+1)*784];
        for (int d = 0; d < 784; d++) s = __fadd_rn(s, __fmul_rn(r0[d], r1[d]));
        snsim[tid] = s;
    }
    __syncthreads();

    if (tid == 0) {
        int used[15]; int breaks[15];
        for (int i = 0; i < 15; i++) { used[i] = 0; breaks[i] = 0; }
        for (int k = 0; k < 3; k++) {
            float best = 1e30f; int bi = 0;
            for (int i = 0; i < 15; i++)
                if (!used[i] && snsim[i] < best) { best = snsim[i]; bi = i; }
            used[bi] = 1; breaks[bi] = 1;
        }
        int g = 0;
        for (int t = 0; t < 16; t++) { if (t > 0) g += breaks[t-1]; sgroups[t] = g; }
        for (int k = 0; k < 4; k++) sgsize[k] = 0;
        for (int t = 0; t < 16; t++) sgsize[sgroups[t]]++;
    }
    __syncthreads();

    for (int d = tid; d < 784; d += 256) {
        float c4[4] = {0.f, 0.f, 0.f, 0.f};
        for (int t = 0; t < 16; t++)
            c4[sgroups[t]] = __fadd_rn(c4[sgroups[t]], sen[t*784 + d]);
        for (int k = 0; k < 4; k++)
            cen[k*784 + d] = __fdiv_rn(c4[k], (float)sgsize[k]);
    }
    __syncthreads();

    if (tid < 4) {
        float s = 0.f;
        const float* ck = &cen[tid*784];
        for (int d = 0; d < 784; d++) s = __fadd_rn(s, __fmul_rn(ck[d], ck[d]));
        scnorm[tid] = fmaxf(__fsqrt_rn(s), 1e-12f);
    }
    __syncthreads();

    for (int i = tid; i < 4*784; i += 256)
        snc[i] = __fdiv_rn(cen[i], scnorm[i / 784]);
    __syncthreads();

    if (tid < 64) {
        int t = tid / 4, k = tid % 4;
        const float* row = &sen[t*784];
        const float* ck = &snc[k*784];
        float s = 0.f;
        for (int d = 0; d < 784; d++)
            s = __fadd_rn(s, __fmul_rn(row[d], ck[d]));
        ssims[t][k] = fminf(fmaxf(s, -1.f), 1.f);
    }
    __syncthreads();

    if (tid < 4) {
        int k = tid;
        float best = -1e30f; int bt = 0;
        for (int t = 0; t < 16; t++) {
            float v = (sgroups[t] == k) ? ssims[t][k] : 0.f;
            if (v > best) { best = v; bt = t; }
        }
        g_tpos[b*NK + k] = bt;
    }
}

// ---------------------------------------------------------------------------
// Kernel 4: gather selected frames
// ---------------------------------------------------------------------------
__global__ __launch_bounds__(256) void k_gather(const float* __restrict__ x, float* __restrict__ out)
{
    int idx = blockIdx.x*256 + threadIdx.x;
    const int total = NB*NC*NK*784;
    if (idx >= total) return;
    int hw4 = idx % 784;
    int t1  = idx / 784;
    int k   = t1 % 4;  t1 /= 4;
    int c   = t1 % 64;
    int b   = t1 / 64;
    int t   = g_tpos[b*NK + k];
    float4 v = __ldg(reinterpret_cast<const float4*>(x) + ((b*NC + c)*NT + t)*784 + hw4);
    reinterpret_cast<float4*>(out)[idx] = v;
}

// ---------------------------------------------------------------------------
extern "C" void kernel_launch(void* const* d_in, const int* in_sizes, int n_in,
                              void* d_out, int out_size)
{
    const float* x  = (const float*)d_in[0];
    const float* w1 = (const float*)d_in[1];
    const float* b1 = (const float*)d_in[2];
    const float* wd = (const float*)d_in[3];
    const float* bd = (const float*)d_in[4];
    const float* w2 = (const float*)d_in[5];
    const float* b2 = (const float*)d_in[6];
    float* out = (float*)d_out;

    cudaFuncSetAttribute(k_conv_pool, cudaFuncAttributeMaxDynamicSharedMemorySize, SMEM1_F*4);
    cudaFuncSetAttribute(k_seg, cudaFuncAttributeMaxDynamicSharedMemorySize, 24*784*4);

    k_conv_pool<<<NB*NT*7, 256, SMEM1_F*4>>>(x, w1, b1);
    k_dw2<<<NB*NT, 784>>>(wd, bd, w2, b2);
    k_seg<<<NB, 256, 24*784*4>>>(nullptr);
    const int total4 = NB*NC*NK*784;
    k_gather<<<(total4 + 255)/256, 256>>>(x, out);
}

// round 9
// speedup vs baseline: 1.5996x; 1.1313x over previous
#include <cuda_runtime.h>

// Problem dims
#define NB   8
#define NC   64
#define NT   16
#define NH   56
#define NW   56
#define NHID 128
#define NHP  28
#define NWP  28
#define NK   4

// Kernel-1 tiling
#define IHT  9
#define NPOS (IHT*NW)
#define CSTR 58
#define RSTR (NC*CSTR + 8)
#define SX_F (IHT*RSTR)
#define WD_F (32*NC*2)
#define BUF_F (32*NPOS)
#define SMEM1_F (SX_F + WD_F + BUF_F)

__device__ float g_pooled[NB*NHID*NT*NHP*NWP];   // [b][ch][t][28*28]
__device__ float g_e[NB*NT*NHP*NWP];             // e values [b][t][784]
__device__ int   g_tpos[NB*NK];

__device__ __forceinline__ unsigned long long ld_u64(const float* p) {
    return *reinterpret_cast<const unsigned long long*>(p);
}

// ---------------------------------------------------------------------------
// Kernel 1: conv1x1 (64->128) + bias + ReLU + maxpool 3x3/s2, exact fp32.
// Per-output: sequential c=0..63 ascending FMA chain from 0 (Eigen-exact).
// 512 threads: 4 position-quarters x 4 channel-subgroups.
// ---------------------------------------------------------------------------
__global__ __launch_bounds__(512, 1) void k_conv_pool(
    const float* __restrict__ x, const float* __restrict__ w1, const float* __restrict__ b1)
{
    extern __shared__ float sm[];
    float* sx  = sm;                 // [9][64][58(+pad)]
    float* swd = sm + SX_F;          // [32][64][2] duplicated weight pairs
    float* buf = sm + SX_F + WD_F;   // [32][504]

    int blk = blockIdx.x;
    int ohg = blk % 7;
    int tt  = (blk / 7) % NT;
    int b   = blk / (7*NT);
    int ih0 = ohg*8 - 1;
    int tid = threadIdx.x;

    // vectorized band load: 14 float4 per (r, cc) row
    const float* xbt = x + (b*NC*NT + tt)*(NH*NW);
    for (int i = tid; i < IHT*NC*14; i += 512) {
        int f4  = i % 14;
        int cc  = (i / 14) % NC;
        int r   = i / (14*NC);
        int ih  = ih0 + r;
        float4 v = make_float4(0.f, 0.f, 0.f, 0.f);
        if (ih >= 0 && ih < NH)
            v = __ldg(reinterpret_cast<const float4*>(xbt + cc*(NT*NH*NW) + ih*NW) + f4);
        float* dst = sx + r*RSTR + cc*CSTR + f4*4;
        *reinterpret_cast<float2*>(dst)     = make_float2(v.x, v.y);
        *reinterpret_cast<float2*>(dst + 2) = make_float2(v.z, v.w);
    }

    int wid  = tid >> 5, lane = tid & 31;
    int half = wid >> 2;      // position quarter (0..3): 128 positions each
    int sub  = wid & 3;       // channel subgroup (0..3): 8 channels each

    const float* xptr[2];
    int  p_[2];
    bool val[2];
    #pragma unroll
    for (int j = 0; j < 2; j++) {
        int p = half*128 + j*64 + 2*lane;
        val[j] = (p < NPOS);
        int pc = val[j] ? p : 0;
        int r  = pc / NW, cl = pc % NW;
        xptr[j] = sx + r*RSTR + cl;
        p_[j] = pc;
    }

    for (int it = 0; it < 4; it++) {
        int ch0 = it*32;
        __syncthreads();
        for (int i = tid; i < 32*NC; i += 512) {
            float v = w1[(ch0 + i/NC)*NC + (i % NC)];
            swd[2*i] = v; swd[2*i+1] = v;
        }
        __syncthreads();

        unsigned long long acc[2][8];
        #pragma unroll
        for (int j = 0; j < 2; j++)
            #pragma unroll
            for (int q = 0; q < 8; q++) acc[j][q] = 0ull;

        const float* wbase = swd + (sub*8)*NC*2;
        #pragma unroll 8
        for (int c = 0; c < NC; c += 2) {
            unsigned long long xv0[2], xv1[2];
            #pragma unroll
            for (int j = 0; j < 2; j++) xv0[j] = ld_u64(xptr[j] + c*CSTR);
            #pragma unroll
            for (int j = 0; j < 2; j++) xv1[j] = ld_u64(xptr[j] + (c+1)*CSTR);
            #pragma unroll
            for (int q = 0; q < 8; q++) {
                ulonglong2 wv = *reinterpret_cast<const ulonglong2*>(wbase + (q*NC + c)*2);
                #pragma unroll
                for (int j = 0; j < 2; j++)
                    asm("fma.rn.f32x2 %0, %1, %2, %0;" : "+l"(acc[j][q]) : "l"(wv.x), "l"(xv0[j]));
                #pragma unroll
                for (int j = 0; j < 2; j++)
                    asm("fma.rn.f32x2 %0, %1, %2, %0;" : "+l"(acc[j][q]) : "l"(wv.y), "l"(xv1[j]));
            }
        }

        #pragma unroll
        for (int q = 0; q < 8; q++) {
            int co = sub*8 + q;
            float bj = b1[ch0 + co];
            #pragma unroll
            for (int j = 0; j < 2; j++) {
                float a0, a1;
                asm("mov.b64 {%0,%1}, %2;" : "=f"(a0), "=f"(a1) : "l"(acc[j][q]));
                a0 = fmaxf(__fadd_rn(a0, bj), 0.f);
                a1 = fmaxf(__fadd_rn(a1, bj), 0.f);
                if (val[j]) {
                    float2 v2 = make_float2(a0, a1);
                    *reinterpret_cast<float2*>(&buf[co*NPOS + p_[j]]) = v2;
                }
            }
        }
        __syncthreads();

        // maxpool 3x3/s2 pad1 (max is order-exact)
        for (int m = tid; m < 4*28*32; m += 512) {
            int oc  = m % 28;
            int orr = (m / 28) & 3;
            int co  = m / 112;
            float mx = 0.f;
            #pragma unroll
            for (int dy = 0; dy < 3; dy++) {
                int lr = 2*orr + dy;
                int gr = ih0 + lr;
                if (gr < 0 || gr >= NH) continue;
                #pragma unroll
                for (int dx = 0; dx < 3; dx++) {
                    int gc = 2*oc - 1 + dx;
                    if (gc < 0 || gc >= NW) continue;
                    mx = fmaxf(mx, buf[co*NPOS + lr*NW + gc]);
                }
            }
            int ch = ch0 + co;
            g_pooled[((b*NHID + ch)*NT + tt)*(NHP*NWP) + (ohg*4 + orr)*NWP + oc] = mx;
        }
    }
}

// ---------------------------------------------------------------------------
// Kernel 2: depthwise 3x3 + bias + ReLU + 1x1 (128->1) + b2.
// Thread-per-position, ch = 0..127 sequential chain (no FMA), taps ascending.
// ---------------------------------------------------------------------------
__global__ __launch_bounds__(784) void k_dw2(
    const float* __restrict__ wd, const float* __restrict__ bd,
    const float* __restrict__ w2, const float* __restrict__ b2)
{
    __shared__ float swdk[NHID*9];
    __shared__ float sbd[NHID], sw2[NHID];

    int bid = blockIdx.x;
    int tt = bid % NT;
    int b  = bid / NT;
    int tid = threadIdx.x;     // position 0..783

    for (int i = tid; i < NHID*9; i += 784) swdk[i] = wd[i];
    if (tid < NHID) { sbd[tid] = bd[tid]; sw2[tid] = w2[tid]; }
    float b2v = b2[0];
    __syncthreads();

    int y = tid / 28, xx = tid % 28;
    int y0 = (y > 0) ? -1 : 0, y1 = (y < 27) ? 1 : 0;
    int x0 = (xx > 0) ? -1 : 0, x1 = (xx < 27) ? 1 : 0;

    const float* base = g_pooled + (b*NHID*NT + tt)*784 + tid;
    const int chstride = NT*784;

    float acc = 0.f;
    #pragma unroll 2
    for (int ch = 0; ch < NHID; ch++) {
        const float* p = base + ch*chstride;
        const float* wk = &swdk[ch*9];
        float v = 0.f;
        #pragma unroll
        for (int ky = y0; ky <= 1; ky++) {
            if (ky > y1) break;
            #pragma unroll
            for (int kx = x0; kx <= 1; kx++) {
                if (kx > x1) break;
                v = __fadd_rn(v, __fmul_rn(wk[(ky+1)*3 + (kx+1)], __ldg(p + ky*28 + kx)));
            }
        }
        float hv = fmaxf(__fadd_rn(v, sbd[ch]), 0.f);
        acc = __fadd_rn(acc, __fmul_rn(sw2[ch], hv));
    }
    g_e[(b*NT + tt)*784 + tid] = __fadd_rn(acc, b2v);
}

// ---------------------------------------------------------------------------
// Kernel 3: segmentation, XLA:CPU-emitter emulation (bit-identical chains).
// ---------------------------------------------------------------------------
__global__ __launch_bounds__(256) void k_seg(const float* __restrict__ dummy)
{
    extern __shared__ float sm[];
    float* sen = sm;                 // [16][784] ne
    float* cen = sm + 16*784;        // [4][784] centers
    float* snc = sm + 20*784;        // [4][784] normalized centers
    __shared__ float snorm[16], snsim[15], scnorm[4];
    __shared__ float ssims[16][4];
    __shared__ int sgroups[16], sgsize[4];

    int b = blockIdx.x, tid = threadIdx.x;

    for (int i = tid; i < 16*784; i += 256)
        sen[i] = g_e[b*NT*784 + i];
    __syncthreads();

    if (tid < 16) {
        float s = 0.f;
        const float* row = &sen[tid*784];
        for (int d = 0; d < 784; d++) s = __fadd_rn(s, __fmul_rn(row[d], row[d]));
        snorm[tid] = fmaxf(__fsqrt_rn(s), 1e-12f);
    }
    __syncthreads();

    for (int i = tid; i < 16*784; i += 256) sen[i] = __fdiv_rn(sen[i], snorm[i / 784]);
    __syncthreads();

    if (tid < 15) {
        float s = 0.f;
        const float* r0 = &sen[tid*784];
        const float* r1 = &sen[(tid+1)*784];
        for (int d = 0; d < 784; d++) s = __fadd_rn(s, __fmul_rn(r0[d], r1[d]));
        snsim[tid] = s;
    }
    __syncthreads();

    if (tid == 0) {
        int used[15]; int breaks[15];
        for (int i = 0; i < 15; i++) { used[i] = 0; breaks[i] = 0; }
        for (int k = 0; k < 3; k++) {
            float best = 1e30f; int bi = 0;
            for (int i = 0; i < 15; i++)
                if (!used[i] && snsim[i] < best) { best = snsim[i]; bi = i; }
            used[bi] = 1; breaks[bi] = 1;
        }
        int g = 0;
        for (int t = 0; t < 16; t++) { if (t > 0) g += breaks[t-1]; sgroups[t] = g; }
        for (int k = 0; k < 4; k++) sgsize[k] = 0;
        for (int t = 0; t < 16; t++) sgsize[sgroups[t]]++;
    }
    __syncthreads();

    for (int d = tid; d < 784; d += 256) {
        float c4[4] = {0.f, 0.f, 0.f, 0.f};
        for (int t = 0; t < 16; t++)
            c4[sgroups[t]] = __fadd_rn(c4[sgroups[t]], sen[t*784 + d]);
        for (int k = 0; k < 4; k++)
            cen[k*784 + d] = __fdiv_rn(c4[k], (float)sgsize[k]);
    }
    __syncthreads();

    if (tid < 4) {
        float s = 0.f;
        const float* ck = &cen[tid*784];
        for (int d = 0; d < 784; d++) s = __fadd_rn(s, __fmul_rn(ck[d], ck[d]));
        scnorm[tid] = fmaxf(__fsqrt_rn(s), 1e-12f);
    }
    __syncthreads();

    for (int i = tid; i < 4*784; i += 256)
        snc[i] = __fdiv_rn(cen[i], scnorm[i / 784]);
    __syncthreads();

    if (tid < 64) {
        int t = tid / 4, k = tid % 4;
        const float* row = &sen[t*784];
        const float* ck = &snc[k*784];
        float s = 0.f;
        for (int d = 0; d < 784; d++)
            s = __fadd_rn(s, __fmul_rn(row[d], ck[d]));
        ssims[t][k] = fminf(fmaxf(s, -1.f), 1.f);
    }
    __syncthreads();

    if (tid < 4) {
        int k = tid;
        float best = -1e30f; int bt = 0;
        for (int t = 0; t < 16; t++) {
            float v = (sgroups[t] == k) ? ssims[t][k] : 0.f;
            if (v > best) { best = v; bt = t; }
        }
        g_tpos[b*NK + k] = bt;
    }
}

// ---------------------------------------------------------------------------
// Kernel 4: gather selected frames
// ---------------------------------------------------------------------------
__global__ __launch_bounds__(256) void k_gather(const float* __restrict__ x, float* __restrict__ out)
{
    int idx = blockIdx.x*256 + threadIdx.x;
    const int total = NB*NC*NK*784;
    if (idx >= total) return;
    int hw4 = idx % 784;
    int t1  = idx / 784;
    int k   = t1 % 4;  t1 /= 4;
    int c   = t1 % 64;
    int b   = t1 / 64;
    int t   = g_tpos[b*NK + k];
    float4 v = __ldg(reinterpret_cast<const float4*>(x) + ((b*NC + c)*NT + t)*784 + hw4);
    reinterpret_cast<float4*>(out)[idx] = v;
}

// ---------------------------------------------------------------------------
extern "C" void kernel_launch(void* const* d_in, const int* in_sizes, int n_in,
                              void* d_out, int out_size)
{
    const float* x  = (const float*)d_in[0];
    const float* w1 = (const float*)d_in[1];
    const float* b1 = (const float*)d_in[2];
    const float* wd = (const float*)d_in[3];
    const float* bd = (const float*)d_in[4];
    const float* w2 = (const float*)d_in[5];
    const float* b2 = (const float*)d_in[6];
    float* out = (float*)d_out;

    cudaFuncSetAttribute(k_conv_pool, cudaFuncAttributeMaxDynamicSharedMemorySize, SMEM1_F*4);
    cudaFuncSetAttribute(k_seg, cudaFuncAttributeMaxDynamicSharedMemorySize, 24*784*4);

    k_conv_pool<<<NB*NT*7, 512, SMEM1_F*4>>>(x, w1, b1);
    k_dw2<<<NB*NT, 784>>>(wd, bd, w2, b2);
    k_seg<<<NB, 256, 24*784*4>>>(nullptr);
    const int total4 = NB*NC*NK*784;
    k_gather<<<(total4 + 255)/256, 256>>>(x, out);
}